// round 14
// baseline (speedup 1.0000x reference)
#include <cuda_runtime.h>

// HierarchyInvertClassifier: out[b,k,h,w] = bias[k] + sum_{c in group k} w[c]*in[b,c,h,w]
// B=8, C=64, H=W=512, K=12. Groups are contiguous channel ranges (static).
//
// HBM-bound pure stream: 512 MiB read + 96 MiB write, zero reuse.
// R14: ILP=8 @ 32-thread blocks. ILP has been monotone in DRAM%
// (1:81.8 -> 2:82.9 -> 4:84.5). 2048 blocks @ ~14 blocks/SM = single wave
// (148*14=2072 >= 2048), so no wave quantization; blocks self-balance on BW.
// Fallback: R13 (ILP=4, TPB=32, 4096 blk) at 94.7us.

#define HW    (512 * 512)
#define HW4   (HW / 4)        // 65536 float4 per plane
#define CCH   64
#define KOUT  12
#define TPB   32              // threads per block (one warp)
#define ILP   8
#define VPB   (ILP * TPB)     // vec positions per block = 256
#define BLKPI (HW4 / VPB)     // blocks per image = 256

__constant__ int kGroupStart[KOUT + 1] = {0, 1, 4, 14, 20, 28, 38, 46, 52, 57, 59, 62, 64};

__global__ __launch_bounds__(TPB)
void hier_invert_kernel(const float4* __restrict__ in4,
                        const float*  __restrict__ w,
                        const float*  __restrict__ bias,
                        float4* __restrict__ out4)
{
    __shared__ float sw[CCH];
    __shared__ float sb[KOUT];
    int t = threadIdx.x;
    sw[t]       = w[t];
    sw[t + 32]  = w[t + 32];
    if (t < KOUT) sb[t] = bias[t];
    __syncwarp();

    int bimg = blockIdx.x >> 8;               // image index (0..7), 256 blocks/image
    int blk  = blockIdx.x & (BLKPI - 1);      // block within image
    int p0   = blk * VPB + t;                 // positions p0 + j*TPB, j=0..7

    const float4* ip = in4 + ((long)bimg * CCH) * HW4 + p0;
    float4*       op = out4 + ((long)bimg * KOUT) * HW4 + p0;

    #pragma unroll
    for (int k = 0; k < KOUT; k++) {
        const int c0 = kGroupStart[k];
        const int c1 = kGroupStart[k + 1];
        float bk = sb[k];
        float4 a0 = make_float4(bk, bk, bk, bk);
        float4 a1 = a0, a2 = a0, a3 = a0, a4 = a0, a5 = a0, a6 = a0, a7 = a0;
        #pragma unroll
        for (int c = c0; c < c1; c++) {
            const float4* p = ip + (long)c * HW4;
            float4 v0 = __ldcs(p);
            float4 v1 = __ldcs(p + 1 * TPB);
            float4 v2 = __ldcs(p + 2 * TPB);
            float4 v3 = __ldcs(p + 3 * TPB);
            float4 v4 = __ldcs(p + 4 * TPB);
            float4 v5 = __ldcs(p + 5 * TPB);
            float4 v6 = __ldcs(p + 6 * TPB);
            float4 v7 = __ldcs(p + 7 * TPB);
            float  wc = sw[c];
            a0.x = fmaf(wc, v0.x, a0.x); a0.y = fmaf(wc, v0.y, a0.y);
            a0.z = fmaf(wc, v0.z, a0.z); a0.w = fmaf(wc, v0.w, a0.w);
            a1.x = fmaf(wc, v1.x, a1.x); a1.y = fmaf(wc, v1.y, a1.y);
            a1.z = fmaf(wc, v1.z, a1.z); a1.w = fmaf(wc, v1.w, a1.w);
            a2.x = fmaf(wc, v2.x, a2.x); a2.y = fmaf(wc, v2.y, a2.y);
            a2.z = fmaf(wc, v2.z, a2.z); a2.w = fmaf(wc, v2.w, a2.w);
            a3.x = fmaf(wc, v3.x, a3.x); a3.y = fmaf(wc, v3.y, a3.y);
            a3.z = fmaf(wc, v3.z, a3.z); a3.w = fmaf(wc, v3.w, a3.w);
            a4.x = fmaf(wc, v4.x, a4.x); a4.y = fmaf(wc, v4.y, a4.y);
            a4.z = fmaf(wc, v4.z, a4.z); a4.w = fmaf(wc, v4.w, a4.w);
            a5.x = fmaf(wc, v5.x, a5.x); a5.y = fmaf(wc, v5.y, a5.y);
            a5.z = fmaf(wc, v5.z, a5.z); a5.w = fmaf(wc, v5.w, a5.w);
            a6.x = fmaf(wc, v6.x, a6.x); a6.y = fmaf(wc, v6.y, a6.y);
            a6.z = fmaf(wc, v6.z, a6.z); a6.w = fmaf(wc, v6.w, a6.w);
            a7.x = fmaf(wc, v7.x, a7.x); a7.y = fmaf(wc, v7.y, a7.y);
            a7.z = fmaf(wc, v7.z, a7.z); a7.w = fmaf(wc, v7.w, a7.w);
        }
        float4* q = op + (long)k * HW4;
        __stcs(q,           a0);
        __stcs(q + 1 * TPB, a1);
        __stcs(q + 2 * TPB, a2);
        __stcs(q + 3 * TPB, a3);
        __stcs(q + 4 * TPB, a4);
        __stcs(q + 5 * TPB, a5);
        __stcs(q + 6 * TPB, a6);
        __stcs(q + 7 * TPB, a7);
    }
}

extern "C" void kernel_launch(void* const* d_in, const int* in_sizes, int n_in,
                              void* d_out, int out_size)
{
    const float* pred_lr = (const float*)d_in[0];   // [8,64,512,512]
    const float* weights = (const float*)d_in[1];   // [64]
    const float* biases  = (const float*)d_in[2];   // [12]
    float* out = (float*)d_out;                     // [8,12,512,512]

    int blocks = 8 * BLKPI;                         // 2048

    hier_invert_kernel<<<blocks, TPB>>>(
        (const float4*)pred_lr, weights, biases, (float4*)out);
}

// round 15
// speedup vs baseline: 1.1026x; 1.1026x over previous
#include <cuda_runtime.h>

// HierarchyInvertClassifier: out[b,k,h,w] = bias[k] + sum_{c in group k} w[c]*in[b,c,h,w]
// B=8, C=64, H=W=512, K=12. Groups are contiguous channel ranges (static).
//
// HBM-bound pure stream: 512 MiB read + 96 MiB write, zero reuse.
// R15 = R13 (measured optimum: ILP=4, 32-thr blocks, 4096 blocks, 72 regs,
// DRAM 84.5%, wall 94.7us) + groups processed in DESCENDING size order:
// high-MLP phases run while all blocks are resident; tiny groups last
// minimize straggler-block tail spread.
// ILP sweep: 1:81.8% 2:82.9% 4:84.5% 8:74.8% (ptxas reg wall) -> 4 is peak.

#define HW    (512 * 512)
#define HW4   (HW / 4)        // 65536 float4 per plane
#define CCH   64
#define KOUT  12
#define TPB   32              // threads per block (one warp)
#define ILP   4
#define VPB   (ILP * TPB)     // vec positions per block = 128
#define BLKPI (HW4 / VPB)     // blocks per image = 512

// Groups sorted by size descending:
//   forest(10,c4)  crop(10,c28)  grass(8,c20)  urban(8,c38)  shrub(6,c14)
//   bare(6,c46)    wetland(5,c52) water(3,c1)  moss(3,c59)   snow(2,c57)
//   cloud(2,c62)   nodata(1,c0)
__constant__ int kOrdK[KOUT]     = {2, 5, 4, 6, 3, 7, 8, 1, 10, 9, 11, 0};
__constant__ int kOrdStart[KOUT] = {4, 28, 20, 38, 14, 46, 52, 1, 59, 57, 62, 0};
__constant__ int kOrdSize[KOUT]  = {10, 10, 8, 8, 6, 6, 5, 3, 3, 2, 2, 1};

__global__ __launch_bounds__(TPB)
void hier_invert_kernel(const float4* __restrict__ in4,
                        const float*  __restrict__ w,
                        const float*  __restrict__ bias,
                        float4* __restrict__ out4)
{
    __shared__ float sw[CCH];
    __shared__ float sb[KOUT];
    int t = threadIdx.x;
    sw[t]       = w[t];
    sw[t + 32]  = w[t + 32];
    if (t < KOUT) sb[t] = bias[t];
    __syncwarp();

    int bimg = blockIdx.x >> 9;               // image index (0..7), 512 blocks/image
    int blk  = blockIdx.x & (BLKPI - 1);      // block within image
    int p0   = blk * VPB + t;                 // positions p0 + j*TPB, j=0..3

    const float4* ip = in4 + ((long)bimg * CCH) * HW4 + p0;
    float4*       op = out4 + ((long)bimg * KOUT) * HW4 + p0;

    #pragma unroll
    for (int g = 0; g < KOUT; g++) {
        const int k  = kOrdK[g];
        const int c0 = kOrdStart[g];
        const int c1 = c0 + kOrdSize[g];
        float bk = sb[k];
        float4 a0 = make_float4(bk, bk, bk, bk);
        float4 a1 = a0, a2 = a0, a3 = a0;
        #pragma unroll
        for (int c = c0; c < c1; c++) {
            const float4* p = ip + (long)c * HW4;
            float4 v0 = __ldcs(p);
            float4 v1 = __ldcs(p + TPB);
            float4 v2 = __ldcs(p + 2 * TPB);
            float4 v3 = __ldcs(p + 3 * TPB);
            float  wc = sw[c];
            a0.x = fmaf(wc, v0.x, a0.x); a0.y = fmaf(wc, v0.y, a0.y);
            a0.z = fmaf(wc, v0.z, a0.z); a0.w = fmaf(wc, v0.w, a0.w);
            a1.x = fmaf(wc, v1.x, a1.x); a1.y = fmaf(wc, v1.y, a1.y);
            a1.z = fmaf(wc, v1.z, a1.z); a1.w = fmaf(wc, v1.w, a1.w);
            a2.x = fmaf(wc, v2.x, a2.x); a2.y = fmaf(wc, v2.y, a2.y);
            a2.z = fmaf(wc, v2.z, a2.z); a2.w = fmaf(wc, v2.w, a2.w);
            a3.x = fmaf(wc, v3.x, a3.x); a3.y = fmaf(wc, v3.y, a3.y);
            a3.z = fmaf(wc, v3.z, a3.z); a3.w = fmaf(wc, v3.w, a3.w);
        }
        float4* q = op + (long)k * HW4;
        __stcs(q, a0);
        __stcs(q + TPB, a1);
        __stcs(q + 2 * TPB, a2);
        __stcs(q + 3 * TPB, a3);
    }
}

extern "C" void kernel_launch(void* const* d_in, const int* in_sizes, int n_in,
                              void* d_out, int out_size)
{
    const float* pred_lr = (const float*)d_in[0];   // [8,64,512,512]
    const float* weights = (const float*)d_in[1];   // [64]
    const float* biases  = (const float*)d_in[2];   // [12]
    float* out = (float*)d_out;                     // [8,12,512,512]

    int blocks = 8 * BLKPI;                         // 4096

    hier_invert_kernel<<<blocks, TPB>>>(
        (const float4*)pred_lr, weights, biases, (float4*)out);
}

// round 16
// speedup vs baseline: 1.1250x; 1.0203x over previous
#include <cuda_runtime.h>

// HierarchyInvertClassifier: out[b,k,h,w] = bias[k] + sum_{c in group k} w[c]*in[b,c,h,w]
// B=8, C=64, H=W=512, K=12. Groups are contiguous channel ranges (static).
//
// HBM-bound pure stream: 512 MiB read + 96 MiB write, zero reuse.
// FINAL = R13, the measured optimum of the full sweep:
//   - ILP=4: four independent LDG.128 streams per channel iteration
//     (ILP DRAM% sweep: 1:81.8, 2:82.9, 4:84.5, 8:74.8 ptxas-reg-wall)
//   - TPB=32 single-warp blocks: ptxas emits tight 72-reg codegen
//     (64-thr ILP=4 needed 104 regs)
//   - 4096 blocks: fine drain-tail granularity (2048-blk variants lose
//     the stream-phase gains to the tail every time)
//   - natural ascending channel order: concurrent blocks sweep adjacent
//     planes -> DRAM row/L2 locality (size-desc reorder cost 2.6pt DRAM)
//   - per-group accumulate+store, __ldcs/__stcs streaming hints
// Measured: wall 94.7us, ncu 90.4us, DRAM 84.5%, HBM 6697 GB/s.

#define HW    (512 * 512)
#define HW4   (HW / 4)        // 65536 float4 per plane
#define CCH   64
#define KOUT  12
#define TPB   32              // threads per block (one warp)
#define ILP   4
#define VPB   (ILP * TPB)     // vec positions per block = 128
#define BLKPI (HW4 / VPB)     // blocks per image = 512

__constant__ int kGroupStart[KOUT + 1] = {0, 1, 4, 14, 20, 28, 38, 46, 52, 57, 59, 62, 64};

__global__ __launch_bounds__(TPB)
void hier_invert_kernel(const float4* __restrict__ in4,
                        const float*  __restrict__ w,
                        const float*  __restrict__ bias,
                        float4* __restrict__ out4)
{
    __shared__ float sw[CCH];
    __shared__ float sb[KOUT];
    int t = threadIdx.x;
    sw[t]       = w[t];
    sw[t + 32]  = w[t + 32];
    if (t < KOUT) sb[t] = bias[t];
    __syncwarp();

    int bimg = blockIdx.x >> 9;               // image index (0..7), 512 blocks/image
    int blk  = blockIdx.x & (BLKPI - 1);      // block within image
    int p0   = blk * VPB + t;                 // positions p0 + j*TPB, j=0..3

    const float4* ip = in4 + ((long)bimg * CCH) * HW4 + p0;
    float4*       op = out4 + ((long)bimg * KOUT) * HW4 + p0;

    #pragma unroll
    for (int k = 0; k < KOUT; k++) {
        const int c0 = kGroupStart[k];
        const int c1 = kGroupStart[k + 1];
        float bk = sb[k];
        float4 a0 = make_float4(bk, bk, bk, bk);
        float4 a1 = a0, a2 = a0, a3 = a0;
        #pragma unroll
        for (int c = c0; c < c1; c++) {
            const float4* p = ip + (long)c * HW4;
            float4 v0 = __ldcs(p);
            float4 v1 = __ldcs(p + TPB);
            float4 v2 = __ldcs(p + 2 * TPB);
            float4 v3 = __ldcs(p + 3 * TPB);
            float  wc = sw[c];
            a0.x = fmaf(wc, v0.x, a0.x); a0.y = fmaf(wc, v0.y, a0.y);
            a0.z = fmaf(wc, v0.z, a0.z); a0.w = fmaf(wc, v0.w, a0.w);
            a1.x = fmaf(wc, v1.x, a1.x); a1.y = fmaf(wc, v1.y, a1.y);
            a1.z = fmaf(wc, v1.z, a1.z); a1.w = fmaf(wc, v1.w, a1.w);
            a2.x = fmaf(wc, v2.x, a2.x); a2.y = fmaf(wc, v2.y, a2.y);
            a2.z = fmaf(wc, v2.z, a2.z); a2.w = fmaf(wc, v2.w, a2.w);
            a3.x = fmaf(wc, v3.x, a3.x); a3.y = fmaf(wc, v3.y, a3.y);
            a3.z = fmaf(wc, v3.z, a3.z); a3.w = fmaf(wc, v3.w, a3.w);
        }
        float4* q = op + (long)k * HW4;
        __stcs(q, a0);
        __stcs(q + TPB, a1);
        __stcs(q + 2 * TPB, a2);
        __stcs(q + 3 * TPB, a3);
    }
}

extern "C" void kernel_launch(void* const* d_in, const int* in_sizes, int n_in,
                              void* d_out, int out_size)
{
    const float* pred_lr = (const float*)d_in[0];   // [8,64,512,512]
    const float* weights = (const float*)d_in[1];   // [64]
    const float* biases  = (const float*)d_in[2];   // [12]
    float* out = (float*)d_out;                     // [8,12,512,512]

    int blocks = 8 * BLKPI;                         // 4096

    hier_invert_kernel<<<blocks, TPB>>>(
        (const float4*)pred_lr, weights, biases, (float4*)out);
}